// round 3
// baseline (speedup 1.0000x reference)
#include <cuda_runtime.h>
#include <cuda_fp16.h>
#include <cstdint>

#define F   16384
#define D   768
#define BSZ 512      // B*S
#define C   16
#define M   (F*C)

#define TI  32       // feature tile in scatter
#define TBS 256      // batch-seq tile in scatter

// Scratch (device globals — no allocations allowed)
__device__ __half g_udec_h[(size_t)F * D];     // up_decoder transposed, fp16: [F, D]
__device__ __half g_ufacts_h[(size_t)F * BSZ]; // up_facts transposed, fp16:   [F, BS]
__device__ float  g_values[M];

// ---------------------------------------------------------------------------
// 32x32 tiled transpose with fp32 -> fp16 convert: src [rows,cols] -> dst [cols,rows]
// ---------------------------------------------------------------------------
__global__ void k_transpose_h(const float* __restrict__ src, __half* __restrict__ dst,
                              int rows, int cols) {
    __shared__ float tile[32][33];
    int x  = blockIdx.x * 32 + threadIdx.x;
    int y0 = blockIdx.y * 32 + threadIdx.y;
#pragma unroll
    for (int k = 0; k < 32; k += 8)
        tile[threadIdx.y + k][threadIdx.x] = src[(size_t)(y0 + k) * cols + x];
    __syncthreads();
    int x2 = blockIdx.y * 32 + threadIdx.x;
    int y2 = blockIdx.x * 32 + threadIdx.y;
#pragma unroll
    for (int k = 0; k < 32; k += 8)
        dst[(size_t)(y2 + k) * rows + x2] =
            __float2half_rn(tile[threadIdx.x][threadIdx.y + k]);
}

// ---------------------------------------------------------------------------
// values[m] = down_encoder[i,:] . udec_h[j,:]   (i = m>>4)
// One warp per connection, 8 warps/block, no smem staging.
// Each thread owns a contiguous 24-element k-segment:
//   down: 6 x float4 (fp32), udec: 3 x uint4 (8 fp16) -> 9 loads in flight.
// ---------------------------------------------------------------------------
__global__ __launch_bounds__(256) void k_values(const float* __restrict__ down_enc,
                                                const int* __restrict__ j_idx) {
    int warp = threadIdx.x >> 5, lane = threadIdx.x & 31;
    int m = blockIdx.x * 8 + warp;
    int i = m >> 4;
    int j = __ldg(j_idx + m);

    const float4* drow = reinterpret_cast<const float4*>(down_enc + (size_t)i * D + lane * 24);
    const uint4*  urow = reinterpret_cast<const uint4*>(g_udec_h + (size_t)j * D + lane * 24);

    // Issue all loads up front (independent)
    float4 d0 = drow[0], d1 = drow[1], d2 = drow[2], d3 = drow[3], d4 = drow[4], d5 = drow[5];
    uint4  u0 = urow[0], u1 = urow[1], u2 = urow[2];

    float acc = 0.f;
    {
        float2 f;
        f = __half22float2(*reinterpret_cast<__half2*>(&u0.x));
        acc = fmaf(f.x, d0.x, fmaf(f.y, d0.y, acc));
        f = __half22float2(*reinterpret_cast<__half2*>(&u0.y));
        acc = fmaf(f.x, d0.z, fmaf(f.y, d0.w, acc));
        f = __half22float2(*reinterpret_cast<__half2*>(&u0.z));
        acc = fmaf(f.x, d1.x, fmaf(f.y, d1.y, acc));
        f = __half22float2(*reinterpret_cast<__half2*>(&u0.w));
        acc = fmaf(f.x, d1.z, fmaf(f.y, d1.w, acc));

        f = __half22float2(*reinterpret_cast<__half2*>(&u1.x));
        acc = fmaf(f.x, d2.x, fmaf(f.y, d2.y, acc));
        f = __half22float2(*reinterpret_cast<__half2*>(&u1.y));
        acc = fmaf(f.x, d2.z, fmaf(f.y, d2.w, acc));
        f = __half22float2(*reinterpret_cast<__half2*>(&u1.z));
        acc = fmaf(f.x, d3.x, fmaf(f.y, d3.y, acc));
        f = __half22float2(*reinterpret_cast<__half2*>(&u1.w));
        acc = fmaf(f.x, d3.z, fmaf(f.y, d3.w, acc));

        f = __half22float2(*reinterpret_cast<__half2*>(&u2.x));
        acc = fmaf(f.x, d4.x, fmaf(f.y, d4.y, acc));
        f = __half22float2(*reinterpret_cast<__half2*>(&u2.y));
        acc = fmaf(f.x, d4.z, fmaf(f.y, d4.w, acc));
        f = __half22float2(*reinterpret_cast<__half2*>(&u2.z));
        acc = fmaf(f.x, d5.x, fmaf(f.y, d5.y, acc));
        f = __half22float2(*reinterpret_cast<__half2*>(&u2.w));
        acc = fmaf(f.x, d5.z, fmaf(f.y, d5.w, acc));
    }
#pragma unroll
    for (int o = 16; o; o >>= 1) acc += __shfl_xor_sync(0xffffffffu, acc, o);
    if (lane == 0) g_values[m] = acc;
}

// ---------------------------------------------------------------------------
// Scatter: out[bs, i] = sum_c values[i*C+c] * ufacts_h[j[i*C+c], bs]
// Tile TI=32 features x TBS=256 bs. 8 warps, each owns 4 features; a lane
// covers 8 bs via one uint4 (8 fp16) gather load per connection.
// fp32 register accumulation; staged through padded smem for fully
// coalesced [bs, F] output stores.
// ---------------------------------------------------------------------------
__global__ __launch_bounds__(256) void k_scatter(const int* __restrict__ j_idx,
                                                 float* __restrict__ out) {
    __shared__ float sacc[TI][TBS + 1];
    __shared__ float sval[TI * C];
    __shared__ int   sj[TI * C];

    int i0  = blockIdx.x * TI;
    int bs0 = blockIdx.y * TBS;
    int tid = threadIdx.x;

    for (int idx = tid; idx < TI * C; idx += 256) {
        sval[idx] = g_values[i0 * C + idx];
        sj[idx]   = j_idx[i0 * C + idx];
    }
    __syncthreads();

    int warp = tid >> 5, lane = tid & 31;
#pragma unroll 1
    for (int ii = warp * 4; ii < warp * 4 + 4; ii++) {
        float a[8];
#pragma unroll
        for (int k = 0; k < 8; k++) a[k] = 0.f;
#pragma unroll
        for (int c = 0; c < C; c++) {
            int   j = sj[ii * C + c];
            float v = sval[ii * C + c];
            uint4 u = *reinterpret_cast<const uint4*>(
                          g_ufacts_h + (size_t)j * BSZ + bs0 + lane * 8);
            float2 f;
            f = __half22float2(*reinterpret_cast<__half2*>(&u.x));
            a[0] = fmaf(v, f.x, a[0]); a[1] = fmaf(v, f.y, a[1]);
            f = __half22float2(*reinterpret_cast<__half2*>(&u.y));
            a[2] = fmaf(v, f.x, a[2]); a[3] = fmaf(v, f.y, a[3]);
            f = __half22float2(*reinterpret_cast<__half2*>(&u.z));
            a[4] = fmaf(v, f.x, a[4]); a[5] = fmaf(v, f.y, a[5]);
            f = __half22float2(*reinterpret_cast<__half2*>(&u.w));
            a[6] = fmaf(v, f.x, a[6]); a[7] = fmaf(v, f.y, a[7]);
        }
#pragma unroll
        for (int k = 0; k < 8; k++) sacc[ii][lane * 8 + k] = a[k];
    }
    __syncthreads();

    // Coalesced stores: consecutive tid -> consecutive feature i
#pragma unroll 4
    for (int idx = tid; idx < TI * TBS; idx += 256) {
        int bs = idx >> 5;          // / TI
        int ii = idx & (TI - 1);
        out[(size_t)(bs0 + bs) * F + i0 + ii] = sacc[ii][bs];
    }
}

// ---------------------------------------------------------------------------
extern "C" void kernel_launch(void* const* d_in, const int* in_sizes, int n_in,
                              void* d_out, int out_size) {
    const float* up_facts = (const float*)d_in[0];  // [B,S,F] = [512, 16384]
    const float* down_enc = (const float*)d_in[1];  // [F, D]
    const float* up_dec   = (const float*)d_in[2];  // [D, F]
    const int*   j_idx    = (const int*)d_in[4];    // [M]
    float* out = (float*)d_out;                     // [B,S,F]

    void* p;
    cudaGetSymbolAddress(&p, g_udec_h);
    __half* udecH = (__half*)p;
    cudaGetSymbolAddress(&p, g_ufacts_h);
    __half* ufactsH = (__half*)p;

    dim3 tb(32, 8);
    // up_decoder [D, F] -> fp16 [F, D]
    k_transpose_h<<<dim3(F / 32, D / 32), tb>>>(up_dec, udecH, D, F);
    // up_facts [BS, F] -> fp16 [F, BS]
    k_transpose_h<<<dim3(F / 32, BSZ / 32), tb>>>(up_facts, ufactsH, BSZ, F);
    // values: one warp per connection
    k_values<<<M / 8, 256>>>(down_enc, j_idx);
    // scatter + output
    k_scatter<<<dim3(F / TI, BSZ / TBS), 256>>>(j_idx, out);
}

// round 4
// speedup vs baseline: 1.3571x; 1.3571x over previous
#include <cuda_runtime.h>
#include <cuda_fp16.h>
#include <cstdint>

#define F   16384
#define D   768
#define BSZ 512      // B*S
#define C   16
#define M   (F*C)

#define TI  64       // feature tile in scatter
#define TBS 128      // batch-seq tile in scatter

// Scratch (device globals — no allocations allowed)
__device__ __half g_udec_h[(size_t)F * D];     // up_decoder transposed, fp16: [F, D]
__device__ __half g_ufacts_h[(size_t)F * BSZ]; // up_facts transposed, fp16:   [F, BS]
__device__ float  g_values[M];

// ---------------------------------------------------------------------------
// Merged grid-stride transpose+convert: handles BOTH
//   up_decoder [D, F] -> g_udec_h   [F, D]   (tiles 0 .. 12287)
//   up_facts   [BSZ,F] -> g_ufacts_h [F, BSZ] (tiles 12288 .. 20479)
// 32x32 tiles, block = (32, 8), ~1-wave grid, loop over tiles.
// ---------------------------------------------------------------------------
#define T_UDEC_TILES (12288)   // (D/32=24) * (F/32=512)
#define T_TOT_TILES  (20480)   // + (BSZ/32=16) * 512

__global__ __launch_bounds__(256) void k_transpose_all(
        const float* __restrict__ up_dec, const float* __restrict__ up_facts) {
    __shared__ float tile[32][33];
    for (int tt = blockIdx.x; tt < T_TOT_TILES; tt += gridDim.x) {
        const float* src; __half* dst; int rows, cols, tx, ty;
        if (tt < T_UDEC_TILES) {
            src = up_dec; dst = g_udec_h; rows = D; cols = F;
            ty = tt >> 9; tx = tt & 511;
        } else {
            int t2 = tt - T_UDEC_TILES;
            src = up_facts; dst = g_ufacts_h; rows = BSZ; cols = F;
            ty = t2 >> 9; tx = t2 & 511;
        }
        int x  = tx * 32 + threadIdx.x;
        int y0 = ty * 32 + threadIdx.y;
#pragma unroll
        for (int k = 0; k < 32; k += 8)
            tile[threadIdx.y + k][threadIdx.x] = src[(size_t)(y0 + k) * cols + x];
        __syncthreads();
        int x2 = ty * 32 + threadIdx.x;
        int y2 = tx * 32 + threadIdx.y;
#pragma unroll
        for (int k = 0; k < 32; k += 8)
            dst[(size_t)(y2 + k) * rows + x2] =
                __float2half_rn(tile[threadIdx.x][threadIdx.y + k]);
        __syncthreads();
    }
}

// ---------------------------------------------------------------------------
// values[i*C+c] = down_encoder[i,:] . udec_h[j_ic,:]
// Warp-autonomous: one warp per feature i, grid-stride. Down row held in
// 24 fp32 registers; 16 connections processed in groups of 4 with 12
// independent coalesced LDG.128 in flight. No smem, no barriers.
// ---------------------------------------------------------------------------
__global__ __launch_bounds__(256, 2) void k_values(const float* __restrict__ down_enc,
                                                   const int* __restrict__ j_idx) {
    int warp = threadIdx.x >> 5, lane = threadIdx.x & 31;
    int gw = blockIdx.x * 8 + warp;
    int nw = gridDim.x * 8;

    for (int i = gw; i < F; i += nw) {
        // Down row -> registers. Thread covers elements [8*lane+256*t, +8) as
        // two float4 (dA pairs with low 4 halfs of the udec uint4, dB with high 4).
        const float4* dr = reinterpret_cast<const float4*>(down_enc + (size_t)i * D);
        float4 dA[3], dB[3];
#pragma unroll
        for (int t = 0; t < 3; t++) {
            dA[t] = dr[t * 64 + lane * 2];
            dB[t] = dr[t * 64 + lane * 2 + 1];
        }
        int jl = 0;
        if (lane < C) jl = j_idx[i * C + lane];

        float acc[C];
#pragma unroll
        for (int c = 0; c < C; c++) acc[c] = 0.f;

#pragma unroll
        for (int g = 0; g < C; g += 4) {
            uint4 u[4][3];
#pragma unroll
            for (int q = 0; q < 4; q++) {
                int j = __shfl_sync(0xffffffffu, jl, g + q);
                const uint4* ur = reinterpret_cast<const uint4*>(g_udec_h + (size_t)j * D);
#pragma unroll
                for (int t = 0; t < 3; t++) u[q][t] = ur[t * 32 + lane];
            }
#pragma unroll
            for (int q = 0; q < 4; q++) {
                float a = acc[g + q];
#pragma unroll
                for (int t = 0; t < 3; t++) {
                    float2 f;
                    f = __half22float2(*reinterpret_cast<__half2*>(&u[q][t].x));
                    a = fmaf(f.x, dA[t].x, fmaf(f.y, dA[t].y, a));
                    f = __half22float2(*reinterpret_cast<__half2*>(&u[q][t].y));
                    a = fmaf(f.x, dA[t].z, fmaf(f.y, dA[t].w, a));
                    f = __half22float2(*reinterpret_cast<__half2*>(&u[q][t].z));
                    a = fmaf(f.x, dB[t].x, fmaf(f.y, dB[t].y, a));
                    f = __half22float2(*reinterpret_cast<__half2*>(&u[q][t].w));
                    a = fmaf(f.x, dB[t].z, fmaf(f.y, dB[t].w, a));
                }
                acc[g + q] = a;
            }
        }
        // 16 independent warp reductions (chains pipeline), then lanes 0..15
        // emit the 16 values (64B coalesced).
#pragma unroll
        for (int c = 0; c < C; c++) {
#pragma unroll
            for (int o = 16; o; o >>= 1)
                acc[c] += __shfl_xor_sync(0xffffffffu, acc[c], o);
        }
#pragma unroll
        for (int c = 0; c < C; c++)
            if (lane == c) g_values[i * C + c] = acc[c];
    }
}

// ---------------------------------------------------------------------------
// Scatter (R2 configuration): out[bs, i] = sum_c values[i*C+c] * ufacts_h[j, bs]
// ---------------------------------------------------------------------------
__global__ __launch_bounds__(256) void k_scatter(const int* __restrict__ j_idx,
                                                 float* __restrict__ out) {
    __shared__ float sacc[TI][TBS + 1];
    __shared__ float sval[TI * C];
    __shared__ int   sj[TI * C];

    int i0  = blockIdx.x * TI;
    int bs0 = blockIdx.y * TBS;
    int tid = threadIdx.x;

    for (int idx = tid; idx < TI * C; idx += 256) {
        sval[idx] = g_values[i0 * C + idx];
        sj[idx]   = j_idx[i0 * C + idx];
    }
    __syncthreads();

    int warp = tid >> 5, lane = tid & 31;
#pragma unroll 1
    for (int ii = warp * 8; ii < warp * 8 + 8; ii++) {
        float a0 = 0.f, a1 = 0.f, a2 = 0.f, a3 = 0.f;
#pragma unroll
        for (int c = 0; c < C; c++) {
            int   j = sj[ii * C + c];
            float v = sval[ii * C + c];
            uint2 u = *reinterpret_cast<const uint2*>(
                          g_ufacts_h + (size_t)j * BSZ + bs0 + lane * 4);
            float2 f;
            f = __half22float2(*reinterpret_cast<__half2*>(&u.x));
            a0 = fmaf(v, f.x, a0); a1 = fmaf(v, f.y, a1);
            f = __half22float2(*reinterpret_cast<__half2*>(&u.y));
            a2 = fmaf(v, f.x, a2); a3 = fmaf(v, f.y, a3);
        }
        sacc[ii][lane * 4 + 0] = a0;
        sacc[ii][lane * 4 + 1] = a1;
        sacc[ii][lane * 4 + 2] = a2;
        sacc[ii][lane * 4 + 3] = a3;
    }
    __syncthreads();

    for (int idx = tid; idx < TI * TBS; idx += 256) {
        int bs = idx >> 6;          // / TI
        int ii = idx & (TI - 1);
        out[(size_t)(bs0 + bs) * F + i0 + ii] = sacc[ii][bs];
    }
}

// ---------------------------------------------------------------------------
extern "C" void kernel_launch(void* const* d_in, const int* in_sizes, int n_in,
                              void* d_out, int out_size) {
    const float* up_facts = (const float*)d_in[0];  // [B,S,F]
    const float* down_enc = (const float*)d_in[1];  // [F, D]
    const float* up_dec   = (const float*)d_in[2];  // [D, F]
    const int*   j_idx    = (const int*)d_in[4];    // [M]
    float* out = (float*)d_out;                     // [B,S,F]

    dim3 tb(32, 8);
    k_transpose_all<<<592, tb>>>(up_dec, up_facts);
    k_values<<<296, 256>>>(down_enc, j_idx);
    k_scatter<<<dim3(F / TI, BSZ / TBS), 256>>>(j_idx, out);
}

// round 5
// speedup vs baseline: 1.4934x; 1.1004x over previous
#include <cuda_runtime.h>
#include <cuda_fp16.h>
#include <cstdint>

#define F   16384
#define D   768
#define BSZ 512      // B*S
#define C   16
#define M   (F*C)

#define TI  64       // feature tile in scatter
#define TBS 128      // batch-seq tile in scatter

// Scratch (device globals — no allocations allowed)
__device__ __half g_udec_h[(size_t)F * D];     // up_decoder transposed, fp16: [F, D]
__device__ __half g_ufacts_h[(size_t)F * BSZ]; // up_facts transposed, fp16:   [F, BS]
__device__ float  g_values[M];

// ---------------------------------------------------------------------------
// 32x32 tiled transpose with fp32 -> fp16 convert: src [rows,cols] -> dst [cols,rows]
// One tile per block (R2 configuration — max block count, latency-tolerant).
// ---------------------------------------------------------------------------
__global__ void k_transpose_h(const float* __restrict__ src, __half* __restrict__ dst,
                              int rows, int cols) {
    __shared__ float tile[32][33];
    int x  = blockIdx.x * 32 + threadIdx.x;
    int y0 = blockIdx.y * 32 + threadIdx.y;
#pragma unroll
    for (int k = 0; k < 32; k += 8)
        tile[threadIdx.y + k][threadIdx.x] = src[(size_t)(y0 + k) * cols + x];
    __syncthreads();
    int x2 = blockIdx.y * 32 + threadIdx.x;
    int y2 = blockIdx.x * 32 + threadIdx.y;
#pragma unroll
    for (int k = 0; k < 32; k += 8)
        dst[(size_t)(y2 + k) * rows + x2] =
            __float2half_rn(tile[threadIdx.x][threadIdx.y + k]);
}

// ---------------------------------------------------------------------------
// values[i*C+c] = down_encoder[i,:] . udec_h[j_ic,:]
// Warp-autonomous: one warp per feature i, grid-stride (1 wave). Down row in
// 24 fp32 registers; 16 connections in groups of 4 with 12 independent
// coalesced LDG.128 in flight. No smem, no barriers.
// ---------------------------------------------------------------------------
__global__ __launch_bounds__(256, 2) void k_values(const float* __restrict__ down_enc,
                                                   const int* __restrict__ j_idx) {
    int warp = threadIdx.x >> 5, lane = threadIdx.x & 31;
    int gw = blockIdx.x * 8 + warp;
    int nw = gridDim.x * 8;

    for (int i = gw; i < F; i += nw) {
        const float4* dr = reinterpret_cast<const float4*>(down_enc + (size_t)i * D);
        float4 dA[3], dB[3];
#pragma unroll
        for (int t = 0; t < 3; t++) {
            dA[t] = dr[t * 64 + lane * 2];
            dB[t] = dr[t * 64 + lane * 2 + 1];
        }
        int jl = 0;
        if (lane < C) jl = j_idx[i * C + lane];

        float acc[C];
#pragma unroll
        for (int c = 0; c < C; c++) acc[c] = 0.f;

#pragma unroll
        for (int g = 0; g < C; g += 4) {
            uint4 u[4][3];
#pragma unroll
            for (int q = 0; q < 4; q++) {
                int j = __shfl_sync(0xffffffffu, jl, g + q);
                const uint4* ur = reinterpret_cast<const uint4*>(g_udec_h + (size_t)j * D);
#pragma unroll
                for (int t = 0; t < 3; t++) u[q][t] = ur[t * 32 + lane];
            }
#pragma unroll
            for (int q = 0; q < 4; q++) {
                float a = acc[g + q];
#pragma unroll
                for (int t = 0; t < 3; t++) {
                    float2 f;
                    f = __half22float2(*reinterpret_cast<__half2*>(&u[q][t].x));
                    a = fmaf(f.x, dA[t].x, fmaf(f.y, dA[t].y, a));
                    f = __half22float2(*reinterpret_cast<__half2*>(&u[q][t].y));
                    a = fmaf(f.x, dA[t].z, fmaf(f.y, dA[t].w, a));
                    f = __half22float2(*reinterpret_cast<__half2*>(&u[q][t].z));
                    a = fmaf(f.x, dB[t].x, fmaf(f.y, dB[t].y, a));
                    f = __half22float2(*reinterpret_cast<__half2*>(&u[q][t].w));
                    a = fmaf(f.x, dB[t].z, fmaf(f.y, dB[t].w, a));
                }
                acc[g + q] = a;
            }
        }
#pragma unroll
        for (int c = 0; c < C; c++) {
#pragma unroll
            for (int o = 16; o; o >>= 1)
                acc[c] += __shfl_xor_sync(0xffffffffu, acc[c], o);
        }
#pragma unroll
        for (int c = 0; c < C; c++)
            if (lane == c) g_values[i * C + c] = acc[c];
    }
}

// ---------------------------------------------------------------------------
// Scatter: out[bs, i] = sum_c values[i*C+c] * ufacts_h[j[i*C+c], bs]
// Tile TI=64 x TBS=128; uint2 (4 fp16) gathers; fp32 accum; padded-smem
// stage for coalesced [bs, F] stores. (R2 configuration — at LTS floor.)
// ---------------------------------------------------------------------------
__global__ __launch_bounds__(256) void k_scatter(const int* __restrict__ j_idx,
                                                 float* __restrict__ out) {
    __shared__ float sacc[TI][TBS + 1];
    __shared__ float sval[TI * C];
    __shared__ int   sj[TI * C];

    int i0  = blockIdx.x * TI;
    int bs0 = blockIdx.y * TBS;
    int tid = threadIdx.x;

    for (int idx = tid; idx < TI * C; idx += 256) {
        sval[idx] = g_values[i0 * C + idx];
        sj[idx]   = j_idx[i0 * C + idx];
    }
    __syncthreads();

    int warp = tid >> 5, lane = tid & 31;
#pragma unroll 1
    for (int ii = warp * 8; ii < warp * 8 + 8; ii++) {
        float a0 = 0.f, a1 = 0.f, a2 = 0.f, a3 = 0.f;
#pragma unroll
        for (int c = 0; c < C; c++) {
            int   j = sj[ii * C + c];
            float v = sval[ii * C + c];
            uint2 u = *reinterpret_cast<const uint2*>(
                          g_ufacts_h + (size_t)j * BSZ + bs0 + lane * 4);
            float2 f;
            f = __half22float2(*reinterpret_cast<__half2*>(&u.x));
            a0 = fmaf(v, f.x, a0); a1 = fmaf(v, f.y, a1);
            f = __half22float2(*reinterpret_cast<__half2*>(&u.y));
            a2 = fmaf(v, f.x, a2); a3 = fmaf(v, f.y, a3);
        }
        sacc[ii][lane * 4 + 0] = a0;
        sacc[ii][lane * 4 + 1] = a1;
        sacc[ii][lane * 4 + 2] = a2;
        sacc[ii][lane * 4 + 3] = a3;
    }
    __syncthreads();

    for (int idx = tid; idx < TI * TBS; idx += 256) {
        int bs = idx >> 6;          // / TI
        int ii = idx & (TI - 1);
        out[(size_t)(bs0 + bs) * F + i0 + ii] = sacc[ii][bs];
    }
}

// ---------------------------------------------------------------------------
extern "C" void kernel_launch(void* const* d_in, const int* in_sizes, int n_in,
                              void* d_out, int out_size) {
    const float* up_facts = (const float*)d_in[0];  // [B,S,F]
    const float* down_enc = (const float*)d_in[1];  // [F, D]
    const float* up_dec   = (const float*)d_in[2];  // [D, F]
    const int*   j_idx    = (const int*)d_in[4];    // [M]
    float* out = (float*)d_out;                     // [B,S,F]

    void* p;
    cudaGetSymbolAddress(&p, g_udec_h);
    __half* udecH = (__half*)p;
    cudaGetSymbolAddress(&p, g_ufacts_h);
    __half* ufactsH = (__half*)p;

    dim3 tb(32, 8);
    // up_decoder [D, F] -> fp16 [F, D]
    k_transpose_h<<<dim3(F / 32, D / 32), tb>>>(up_dec, udecH, D, F);
    // up_facts [BS, F] -> fp16 [F, BS]
    k_transpose_h<<<dim3(F / 32, BSZ / 32), tb>>>(up_facts, ufactsH, BSZ, F);
    // values: one warp per feature, single wave
    k_values<<<296, 256>>>(down_enc, j_idx);
    // scatter + output
    k_scatter<<<dim3(F / TI, BSZ / TBS), 256>>>(j_idx, out);
}

// round 6
// speedup vs baseline: 1.5380x; 1.0299x over previous
#include <cuda_runtime.h>
#include <cuda_fp16.h>
#include <cstdint>

#define F   16384
#define D   768
#define BSZ 512      // B*S
#define C   16
#define M   (F*C)

#define TI  64       // feature tile in scatter
#define TBS 128      // batch-seq tile in scatter

// Scratch (device globals — no allocations allowed)
__device__ __half g_udec_h[(size_t)F * D];     // up_decoder transposed, fp16: [F, D]
__device__ __half g_ufacts_h[(size_t)F * BSZ]; // up_facts transposed, fp16:   [F, BS]
__device__ float  g_values[M];

// ---------------------------------------------------------------------------
// Persistent pipelined transpose+convert. Handles BOTH transposes as one
// grid-stride tile stream; double-buffered smem, ONE barrier per tile, and
// the next tile's LDGs issue before the current tile's convert/store phase.
//   tiles [0, 12288):  up_decoder [D, F]  -> g_udec_h   [F, D]
//   tiles [12288, 20480): up_facts [BSZ,F]-> g_ufacts_h [F, BSZ]
// ---------------------------------------------------------------------------
#define T_UDEC_TILES 12288   // (D/32) * (F/32)
#define T_TOT_TILES  20480
#define T_GRID       1184    // 8 blocks/SM * 148

struct TileMeta {
    const float* src;
    __half*      dst;
    int rows, cols, tx, ty;
};

__device__ __forceinline__ TileMeta decode_tile(int tt, const float* up_dec,
                                                const float* up_facts) {
    TileMeta m;
    if (tt < T_UDEC_TILES) {
        m.src = up_dec;   m.dst = g_udec_h;   m.rows = D;   m.cols = F;
        m.ty = tt >> 9;   m.tx = tt & 511;
    } else {
        int t2 = tt - T_UDEC_TILES;
        m.src = up_facts; m.dst = g_ufacts_h; m.rows = BSZ; m.cols = F;
        m.ty = t2 >> 9;   m.tx = t2 & 511;
    }
    return m;
}

__global__ __launch_bounds__(256) void k_transpose_pipe(
        const float* __restrict__ up_dec, const float* __restrict__ up_facts) {
    __shared__ float buf[2][32][33];
    int lx = threadIdx.x, ly = threadIdx.y;

    int tt = blockIdx.x;
    if (tt >= T_TOT_TILES) return;

    TileMeta cur = decode_tile(tt, up_dec, up_facts);
    float v[4];
#pragma unroll
    for (int k = 0; k < 4; k++)
        v[k] = cur.src[(size_t)(cur.ty * 32 + ly + 8 * k) * cur.cols + cur.tx * 32 + lx];

    int p = 0;
    while (true) {
#pragma unroll
        for (int k = 0; k < 4; k++)
            buf[p][ly + 8 * k][lx] = v[k];

        int tn = tt + T_GRID;
        __syncthreads();

        // Issue next tile's global loads early (overlap with store phase)
        TileMeta nxt;
        float nv[4];
        bool have = (tn < T_TOT_TILES);
        if (have) {
            nxt = decode_tile(tn, up_dec, up_facts);
#pragma unroll
            for (int k = 0; k < 4; k++)
                nv[k] = nxt.src[(size_t)(nxt.ty * 32 + ly + 8 * k) * nxt.cols + nxt.tx * 32 + lx];
        }

        // Convert + store current tile (transposed)
#pragma unroll
        for (int k = 0; k < 4; k++)
            cur.dst[(size_t)(cur.tx * 32 + ly + 8 * k) * cur.rows + cur.ty * 32 + lx] =
                __float2half_rn(buf[p][lx][ly + 8 * k]);

        if (!have) break;
        p ^= 1;
        tt = tn;
        cur = nxt;
#pragma unroll
        for (int k = 0; k < 4; k++) v[k] = nv[k];
    }
}

// ---------------------------------------------------------------------------
// values[i*C+c] = down_encoder[i,:] . udec_h[j_ic,:]
// Warp-autonomous: one warp per feature i, single-wave grid-stride.
// ---------------------------------------------------------------------------
__global__ __launch_bounds__(256, 2) void k_values(const float* __restrict__ down_enc,
                                                   const int* __restrict__ j_idx) {
    int warp = threadIdx.x >> 5, lane = threadIdx.x & 31;
    int gw = blockIdx.x * 8 + warp;
    int nw = gridDim.x * 8;

    for (int i = gw; i < F; i += nw) {
        const float4* dr = reinterpret_cast<const float4*>(down_enc + (size_t)i * D);
        float4 dA[3], dB[3];
#pragma unroll
        for (int t = 0; t < 3; t++) {
            dA[t] = dr[t * 64 + lane * 2];
            dB[t] = dr[t * 64 + lane * 2 + 1];
        }
        int jl = 0;
        if (lane < C) jl = j_idx[i * C + lane];

        float acc[C];
#pragma unroll
        for (int c = 0; c < C; c++) acc[c] = 0.f;

#pragma unroll
        for (int g = 0; g < C; g += 4) {
            uint4 u[4][3];
#pragma unroll
            for (int q = 0; q < 4; q++) {
                int j = __shfl_sync(0xffffffffu, jl, g + q);
                const uint4* ur = reinterpret_cast<const uint4*>(g_udec_h + (size_t)j * D);
#pragma unroll
                for (int t = 0; t < 3; t++) u[q][t] = ur[t * 32 + lane];
            }
#pragma unroll
            for (int q = 0; q < 4; q++) {
                float a = acc[g + q];
#pragma unroll
                for (int t = 0; t < 3; t++) {
                    float2 f;
                    f = __half22float2(*reinterpret_cast<__half2*>(&u[q][t].x));
                    a = fmaf(f.x, dA[t].x, fmaf(f.y, dA[t].y, a));
                    f = __half22float2(*reinterpret_cast<__half2*>(&u[q][t].y));
                    a = fmaf(f.x, dA[t].z, fmaf(f.y, dA[t].w, a));
                    f = __half22float2(*reinterpret_cast<__half2*>(&u[q][t].z));
                    a = fmaf(f.x, dB[t].x, fmaf(f.y, dB[t].y, a));
                    f = __half22float2(*reinterpret_cast<__half2*>(&u[q][t].w));
                    a = fmaf(f.x, dB[t].z, fmaf(f.y, dB[t].w, a));
                }
                acc[g + q] = a;
            }
        }
#pragma unroll
        for (int c = 0; c < C; c++) {
#pragma unroll
            for (int o = 16; o; o >>= 1)
                acc[c] += __shfl_xor_sync(0xffffffffu, acc[c], o);
        }
#pragma unroll
        for (int c = 0; c < C; c++)
            if (lane == c) g_values[i * C + c] = acc[c];
    }
}

// ---------------------------------------------------------------------------
// Scatter: out[bs, i] = sum_c values[i*C+c] * ufacts_h[j[i*C+c], bs]
// ---------------------------------------------------------------------------
__global__ __launch_bounds__(256) void k_scatter(const int* __restrict__ j_idx,
                                                 float* __restrict__ out) {
    __shared__ float sacc[TI][TBS + 1];
    __shared__ float sval[TI * C];
    __shared__ int   sj[TI * C];

    int i0  = blockIdx.x * TI;
    int bs0 = blockIdx.y * TBS;
    int tid = threadIdx.x;

    for (int idx = tid; idx < TI * C; idx += 256) {
        sval[idx] = g_values[i0 * C + idx];
        sj[idx]   = j_idx[i0 * C + idx];
    }
    __syncthreads();

    int warp = tid >> 5, lane = tid & 31;
#pragma unroll 1
    for (int ii = warp * 8; ii < warp * 8 + 8; ii++) {
        float a0 = 0.f, a1 = 0.f, a2 = 0.f, a3 = 0.f;
#pragma unroll
        for (int c = 0; c < C; c++) {
            int   j = sj[ii * C + c];
            float v = sval[ii * C + c];
            uint2 u = *reinterpret_cast<const uint2*>(
                          g_ufacts_h + (size_t)j * BSZ + bs0 + lane * 4);
            float2 f;
            f = __half22float2(*reinterpret_cast<__half2*>(&u.x));
            a0 = fmaf(v, f.x, a0); a1 = fmaf(v, f.y, a1);
            f = __half22float2(*reinterpret_cast<__half2*>(&u.y));
            a2 = fmaf(v, f.x, a2); a3 = fmaf(v, f.y, a3);
        }
        sacc[ii][lane * 4 + 0] = a0;
        sacc[ii][lane * 4 + 1] = a1;
        sacc[ii][lane * 4 + 2] = a2;
        sacc[ii][lane * 4 + 3] = a3;
    }
    __syncthreads();

    for (int idx = tid; idx < TI * TBS; idx += 256) {
        int bs = idx >> 6;          // / TI
        int ii = idx & (TI - 1);
        out[(size_t)(bs0 + bs) * F + i0 + ii] = sacc[ii][bs];
    }
}

// ---------------------------------------------------------------------------
extern "C" void kernel_launch(void* const* d_in, const int* in_sizes, int n_in,
                              void* d_out, int out_size) {
    const float* up_facts = (const float*)d_in[0];  // [B,S,F]
    const float* down_enc = (const float*)d_in[1];  // [F, D]
    const float* up_dec   = (const float*)d_in[2];  // [D, F]
    const int*   j_idx    = (const int*)d_in[4];    // [M]
    float* out = (float*)d_out;                     // [B,S,F]

    dim3 tb(32, 8);
    k_transpose_pipe<<<T_GRID, tb>>>(up_dec, up_facts);
    k_values<<<296, 256>>>(down_enc, j_idx);
    k_scatter<<<dim3(F / TI, BSZ / TBS), 256>>>(j_idx, out);
}